// round 2
// baseline (speedup 1.0000x reference)
#include <cuda_runtime.h>

#define NQ        14
#define NSTATE    16384      // 2^14
#define NTHREADS  256

// Shared memory layout (floats):
//  state[16384] | Thi[256] | Tlo[64] | c1[14] | s1[14] | red[8*14] | c0[14] | s0[14]
#define SM_FLOATS (NSTATE + 256 + 64 + 14 + 14 + 112 + 14 + 14)
#define SM_BYTES  (SM_FLOATS * 4)

__global__ void __launch_bounds__(NTHREADS, 3)
qsim_kernel(const float* __restrict__ x, const float* __restrict__ wts,
            float* __restrict__ out)
{
    extern __shared__ float sm[];
    float* state = sm;                 // 16384
    float* Thi   = sm + NSTATE;        // 256
    float* Tlo   = Thi + 256;          // 64
    float* c1    = Tlo + 64;           // 14  (layer-1 cos)
    float* s1    = c1 + NQ;            // 14  (layer-1 sin)
    float* red   = s1 + NQ;            // 8*14
    float* c0    = red + 8 * NQ;       // 14  (fused encoding+layer0 cos)
    float* s0    = c0 + NQ;            // 14

    const int b   = blockIdx.x;
    const int tid = threadIdx.x;

    // ---- angles: fuse x-RY with layer-0 RY (same wire => angles add) ----
    if (tid < NQ) {
        float h0 = 0.5f * (x[b * NQ + tid] + wts[tid]);
        float cc, ss;
        sincosf(h0, &ss, &cc);
        c0[tid] = cc; s0[tid] = ss;
        float h1 = 0.5f * wts[NQ + tid];
        sincosf(h1, &ss, &cc);
        c1[tid] = cc; s1[tid] = ss;
    }
    __syncthreads();

    // ---- factor tables for the product state ----
    // bit k of index <-> wire (13-k).  Tlo covers bits 0..5, Thi bits 6..13.
    if (tid < 64) {
        float p = 1.0f;
        #pragma unroll
        for (int k = 0; k < 6; k++)
            p *= ((tid >> k) & 1) ? s0[13 - k] : c0[13 - k];
        Tlo[tid] = p;
    }
    {
        float p = 1.0f;
        #pragma unroll
        for (int k = 0; k < 8; k++)
            p *= ((tid >> k) & 1) ? s0[7 - k] : c0[7 - k];
        Thi[tid] = p;
    }
    __syncthreads();

    // ---- generate product state directly (28 gates folded into 1 pass) ----
    float4* st4 = (float4*)state;
    const float4* Tlo4 = (const float4*)Tlo;
    for (int i = tid; i < NSTATE / 4; i += NTHREADS) {
        int base = i << 2;
        float hv = Thi[base >> 6];
        float4 lo = Tlo4[(base & 63) >> 2];
        float4 v;
        v.x = hv * lo.x; v.y = hv * lo.y; v.z = hv * lo.z; v.w = hv * lo.w;
        st4[i] = v;
    }
    __syncthreads();

    // ---- layer-1 RYs with CNOT-chain folded into index algebra ----
    // After 1 chain, array loc holds logical state C(loc), C(s)_t = xor of s bits t..13.
    // RY on wire w (t = 13-w) pairs loc with loc ^ m, m = C^{-1}(e_t) = e_t|e_{t-1} (e_0 if t==0).
    // Logical-0 member decided by sigma = parity(loc & bits[t+1..13]) with bit t of loc = 0.
    for (int wq = 0; wq < NQ; wq++) {
        const int t    = 13 - wq;
        const int m    = (t == 0) ? 1 : ((1 << t) | (1 << (t - 1)));
        const int Shi  = 0x3FFF & ~((1 << (t + 1)) - 1);
        const float c  = c1[wq];
        const float s  = s1[wq];
        if (t >= 3) {
            // float4 path: pairs are 16B-aligned groups, sign constant within group
            for (int g = tid; g < NSTATE / 8; g += NTHREADS) {
                int k   = g << 2;
                int loc = ((k >> t) << (t + 1)) | (k & ((1 << t) - 1));
                int prt = loc ^ m;
                float se = (__popc(loc & Shi) & 1) ? -s : s;
                float4 u = *(float4*)(state + loc);
                float4 v = *(float4*)(state + prt);
                float4 nu, nv;
                nu.x = c * u.x - se * v.x;  nv.x = se * u.x + c * v.x;
                nu.y = c * u.y - se * v.y;  nv.y = se * u.y + c * v.y;
                nu.z = c * u.z - se * v.z;  nv.z = se * u.z + c * v.z;
                nu.w = c * u.w - se * v.w;  nv.w = se * u.w + c * v.w;
                *(float4*)(state + loc) = nu;
                *(float4*)(state + prt) = nv;
            }
        } else {
            for (int k = tid; k < NSTATE / 2; k += NTHREADS) {
                int loc = ((k >> t) << (t + 1)) | (k & ((1 << t) - 1));
                int prt = loc ^ m;
                float se = (__popc(loc & Shi) & 1) ? -s : s;
                float u = state[loc], v = state[prt];
                state[loc] = c * u - se * v;
                state[prt] = se * u + c * v;
            }
        }
        __syncthreads();
    }

    // ---- fused measurement: <Z_w> = sum p(loc)*(-1)^parity(loc & M_w),
    //      M_w = bits {t, t+2, ...} (second CNOT chain folded in) ----
    float acc[NQ];
    #pragma unroll
    for (int w = 0; w < NQ; w++) acc[w] = 0.0f;

    for (int i = tid; i < NSTATE / 4; i += NTHREADS) {
        int loc = i << 2;
        float4 a = st4[i];
        float p0 = a.x * a.x, p1 = a.y * a.y, p2 = a.z * a.z, p3 = a.w * a.w;
        float sAll = (p0 + p1) + (p2 + p3);
        float sB0  = (p0 - p1) + (p2 - p3);   // flips with bit0 (t==0 case)
        float sB1  = (p0 + p1) - (p2 + p3);   // flips with bit1 (t==1 case)
        #pragma unroll
        for (int w = 0; w < NQ; w++) {
            const int t = 13 - w;
            int M = 0;
            #pragma unroll
            for (int j = t; j <= 13; j += 2) M |= (1 << j);   // compile-time
            const int Mh = M & ~3;
            float contrib = (t == 0) ? sB0 : ((t == 1) ? sB1 : sAll);
            acc[w] += (__popc(loc & Mh) & 1) ? -contrib : contrib;
        }
    }

    // warp butterfly reduce, then cross-warp via smem
    #pragma unroll
    for (int w = 0; w < NQ; w++) {
        float v = acc[w];
        #pragma unroll
        for (int o = 16; o > 0; o >>= 1)
            v += __shfl_xor_sync(0xFFFFFFFF, v, o);
        if ((tid & 31) == 0) red[(tid >> 5) * NQ + w] = v;
    }
    __syncthreads();
    if (tid < NQ) {
        float v = 0.0f;
        #pragma unroll
        for (int r = 0; r < 8; r++) v += red[r * NQ + tid];
        out[b * NQ + tid] = v;
    }
}

extern "C" void kernel_launch(void* const* d_in, const int* in_sizes, int n_in,
                              void* d_out, int out_size)
{
    const float* x   = (const float*)d_in[0];   // [B, 14]
    const float* wts = (const float*)d_in[1];   // [2, 14]
    float* out = (float*)d_out;                 // [B, 14]
    int B = in_sizes[0] / NQ;

    cudaFuncSetAttribute(qsim_kernel,
                         cudaFuncAttributeMaxDynamicSharedMemorySize, SM_BYTES);
    qsim_kernel<<<B, NTHREADS, SM_BYTES>>>(x, wts, out);
}

// round 3
// speedup vs baseline: 1.5618x; 1.5618x over previous
#include <cuda_runtime.h>

#define NQ        14
#define NSTATE    16384
#define NTHREADS  256

// smem floats: state | Thi(256) | Tlo(64) | c0,s0,c1,s1 (4*14) | red(8*14)
#define SM_FLOATS (NSTATE + 256 + 64 + 4*NQ + 8*NQ)
#define SM_BYTES  (SM_FLOATS * 4)

__device__ __forceinline__ void rot4(float4& u, float4& v, float c, float se)
{
    float ux = u.x, uy = u.y, uz = u.z, uw = u.w;
    u.x = c*ux - se*v.x;  u.y = c*uy - se*v.y;
    u.z = c*uz - se*v.z;  u.w = c*uw - se*v.w;
    v.x = se*ux + c*v.x;  v.y = se*uy + c*v.y;
    v.z = se*uz + c*v.z;  v.w = se*uw + c*v.w;
}

__device__ __forceinline__ void rot1(float& u, float& v, float c, float se)
{
    float uu = u;
    u = c*uu - se*v;
    v = se*uu + c*v;
}

// Apply gates t=T, T-1, T-2 in one pass over 8-element (float4-group) cosets.
// Group masks: A=3<<(T-3), B=3<<(T-4), C=3<<(T-5). Requires T >= 7.
// If GEN, elements are generated from the product tables instead of loaded.
template<int T, bool GEN>
__device__ __forceinline__ void triple_pass(float4* st4, const float* Thi,
                                            const float4* Tlo4,
                                            float cT, float sT,
                                            float cU, float sU,
                                            float cV, float sV, int tid)
{
    const int A  = 3 << (T-3);
    const int B  = 3 << (T-4);
    const int C  = 3 << (T-5);
    const int HI = 0x3FFF & ~((1 << (T+1)) - 1);
    for (int k = tid; k < NSTATE/32; k += NTHREADS) {
        int base = ((k >> (T-4)) << (T-1)) | (k & ((1 << (T-4)) - 1));
        float sg  = (__popc((base << 2) & HI) & 1) ? -1.0f : 1.0f;
        float seT = sg*sT, seU = sg*sU, seV = sg*sV;
        int g0 = base,     g1 = base^A,    g2 = base^B,    g3 = base^C;
        int g4 = base^A^B, g5 = base^A^C,  g6 = base^B^C,  g7 = base^A^B^C;
        float4 e0, e1, e2, e3, e4, e5, e6, e7;
        if (GEN) {
            float4 lo = Tlo4[base & 15];   // masks don't touch low 4 G-bits
            float h0 = Thi[g0 >> 4], h1 = Thi[g1 >> 4], h2 = Thi[g2 >> 4], h3 = Thi[g3 >> 4];
            float h4 = Thi[g4 >> 4], h5 = Thi[g5 >> 4], h6 = Thi[g6 >> 4], h7 = Thi[g7 >> 4];
            e0 = make_float4(h0*lo.x, h0*lo.y, h0*lo.z, h0*lo.w);
            e1 = make_float4(h1*lo.x, h1*lo.y, h1*lo.z, h1*lo.w);
            e2 = make_float4(h2*lo.x, h2*lo.y, h2*lo.z, h2*lo.w);
            e3 = make_float4(h3*lo.x, h3*lo.y, h3*lo.z, h3*lo.w);
            e4 = make_float4(h4*lo.x, h4*lo.y, h4*lo.z, h4*lo.w);
            e5 = make_float4(h5*lo.x, h5*lo.y, h5*lo.z, h5*lo.w);
            e6 = make_float4(h6*lo.x, h6*lo.y, h6*lo.z, h6*lo.w);
            e7 = make_float4(h7*lo.x, h7*lo.y, h7*lo.z, h7*lo.w);
        } else {
            e0 = st4[g0]; e1 = st4[g1]; e2 = st4[g2]; e3 = st4[g3];
            e4 = st4[g4]; e5 = st4[g5]; e6 = st4[g6]; e7 = st4[g7];
        }
        // gate T:    pairs differ by bits (T,T-1); sign constant
        rot4(e0, e1, cT,  seT); rot4(e2, e4, cT,  seT);
        rot4(e3, e5, cT,  seT); rot4(e6, e7, cT,  seT);
        // gate T-1:  pairs differ by bits (T-1,T-2); sign flips with bit T
        rot4(e0, e2, cU,  seU); rot4(e4, e1, cU, -seU);
        rot4(e3, e6, cU,  seU); rot4(e7, e5, cU, -seU);
        // gate T-2:  pairs differ by bits (T-2,T-3); sign flips with bit T^T-1
        rot4(e0, e3, cV,  seV); rot4(e1, e5, cV,  seV);
        rot4(e6, e2, cV, -seV); rot4(e7, e4, cV, -seV);
        st4[g0] = e0; st4[g1] = e1; st4[g2] = e2; st4[g3] = e3;
        st4[g4] = e4; st4[g5] = e5; st4[g6] = e6; st4[g7] = e7;
    }
}

__global__ void __launch_bounds__(NTHREADS, 3)
qsim_kernel(const float* __restrict__ x, const float* __restrict__ wts,
            float* __restrict__ out)
{
    extern __shared__ float sm[];
    float* state = sm;
    float* Thi   = sm + NSTATE;
    float* Tlo   = Thi + 256;
    float* c0    = Tlo + 64;
    float* s0    = c0 + NQ;
    float* c1    = s0 + NQ;
    float* s1    = c1 + NQ;
    float* red   = s1 + NQ;

    const int b   = blockIdx.x;
    const int tid = threadIdx.x;

    // fused encoding + layer-0 angles; layer-1 angles
    if (tid < NQ) {
        float cc, ss;
        sincosf(0.5f * (x[b*NQ + tid] + wts[tid]), &ss, &cc);
        c0[tid] = cc; s0[tid] = ss;
        sincosf(0.5f * wts[NQ + tid], &ss, &cc);
        c1[tid] = cc; s1[tid] = ss;
    }
    __syncthreads();

    // product-state factor tables: Tlo bits 0..5, Thi bits 6..13 (bit k <-> wire 13-k)
    if (tid < 64) {
        float p = 1.0f;
        #pragma unroll
        for (int k = 0; k < 6; k++)
            p *= ((tid >> k) & 1) ? s0[13 - k] : c0[13 - k];
        Tlo[tid] = p;
    }
    {
        float p = 1.0f;
        #pragma unroll
        for (int k = 0; k < 8; k++)
            p *= ((tid >> k) & 1) ? s0[7 - k] : c0[7 - k];
        Thi[tid] = p;
    }
    __syncthreads();

    float4* st4 = (float4*)state;
    const float4* Tlo4 = (const float4*)Tlo;

    // Pass 1: generate + gates t=13,12,11 (wq 0,1,2)
    triple_pass<13, true >(st4, Thi, Tlo4, c1[0], s1[0], c1[1], s1[1], c1[2], s1[2], tid);
    __syncthreads();
    // Pass 2: gates t=10,9,8 (wq 3,4,5)
    triple_pass<10, false>(st4, Thi, Tlo4, c1[3], s1[3], c1[4], s1[4], c1[5], s1[5], tid);
    __syncthreads();
    // Pass 3: gates t=7,6,5 (wq 6,7,8)
    triple_pass<7,  false>(st4, Thi, Tlo4, c1[6], s1[6], c1[7], s1[7], c1[8], s1[8], tid);
    __syncthreads();

    // Pass 4: gates t=4,3 (wq 9,10) — masks span bits 4..2, i.e. group bits 2..0.
    // Each aligned 8-group block holds two complete quads; contiguous loads.
    {
        const float c4 = c1[9],  s4 = s1[9];
        const float c3 = c1[10], s3 = s1[10];
        for (int k = tid; k < NSTATE/32; k += NTHREADS) {
            int gb = k << 3;
            float sg  = (__popc((gb << 2) & 0x3FE0) & 1) ? -1.0f : 1.0f;
            float se4 = sg*s4, se3 = sg*s3;
            float4 e0 = st4[gb+0], e1 = st4[gb+1], e2 = st4[gb+2], e3 = st4[gb+3];
            float4 e4 = st4[gb+4], e5 = st4[gb+5], e6 = st4[gb+6], e7 = st4[gb+7];
            // gate 4: pairs j ^ 6 (u has bit4=0), constant sign
            rot4(e0, e6, c4, se4); rot4(e1, e7, c4, se4);
            rot4(e2, e4, c4, se4); rot4(e3, e5, c4, se4);
            // gate 3: pairs j ^ 3 (u has bit3=0), sign flips with bit4
            rot4(e0, e3, c3,  se3); rot4(e1, e2, c3,  se3);
            rot4(e4, e7, c3, -se3); rot4(e5, e6, c3, -se3);
            st4[gb+0] = e0; st4[gb+1] = e1; st4[gb+2] = e2; st4[gb+3] = e3;
            st4[gb+4] = e4; st4[gb+5] = e5; st4[gb+6] = e6; st4[gb+7] = e7;
        }
    }
    __syncthreads();

    // Pass 5: gates t=2,1,0 (wq 11,12,13) fused with measurement; never store state.
    float acc[NQ];
    #pragma unroll
    for (int w = 0; w < NQ; w++) acc[w] = 0.0f;
    {
        const float c2 = c1[11], s2 = s1[11];
        const float cg = c1[12], sgn1 = s1[12];
        const float ch = c1[13], sgn0 = s1[13];
        for (int k = tid; k < NSTATE/8; k += NTHREADS) {
            float4 a = st4[2*k], bb = st4[2*k + 1];
            float q0 = a.x,  q1 = a.y,  q2 = a.z,  q3 = a.w;
            float q4 = bb.x, q5 = bb.y, q6 = bb.z, q7 = bb.w;
            int loc = k << 3;
            float sg = (__popc(loc & 0x3FF8) & 1) ? -1.0f : 1.0f;
            // gate t=2: pairs j^6, constant sign
            float se = sg * s2;
            rot1(q0, q6, c2, se); rot1(q1, q7, c2, se);
            rot1(q2, q4, c2, se); rot1(q3, q5, c2, se);
            // gate t=1: pairs j^3, sign flips with bit2
            se = sg * sgn1;
            rot1(q0, q3, cg,  se); rot1(q1, q2, cg,  se);
            rot1(q4, q7, cg, -se); rot1(q5, q6, cg, -se);
            // gate t=0: pairs j^1, sign flips with parity(bits 2,1)
            se = sg * sgn0;
            rot1(q0, q1, ch,  se); rot1(q2, q3, ch, -se);
            rot1(q4, q5, ch, -se); rot1(q6, q7, ch,  se);
            // probabilities + in-octet parity sums
            float p0 = q0*q0, p1 = q1*q1, p2 = q2*q2, p3 = q3*q3;
            float p4 = q4*q4, p5 = q5*q5, p6 = q6*q6, p7 = q7*q7;
            float lo_  = (p0 + p1) + (p2 + p3);
            float hi_  = (p4 + p5) + (p6 + p7);
            float P  = lo_ + hi_;
            float E2 = lo_ - hi_;                                   // (-1)^bit2
            float E1 = ((p0 + p1) - (p2 + p3)) + ((p4 + p5) - (p6 + p7)); // (-1)^bit1
            float E0 = ((p0 - p1) + (p2 - p3)) - ((p4 - p5) + (p6 - p7)); // (-1)^popc(j&5)
            #pragma unroll
            for (int w = 0; w < NQ; w++) {
                const int t = 13 - w;
                int M = 0;
                #pragma unroll
                for (int j = t; j <= 13; j += 2) M |= (1 << j);
                const int Mh = M & ~7;
                float contrib = (t == 0) ? E0 : (t == 1) ? E1 : (t == 2) ? E2 : P;
                acc[w] += (__popc(loc & Mh) & 1) ? -contrib : contrib;
            }
        }
    }

    // reduce: warp butterfly then cross-warp via smem
    #pragma unroll
    for (int w = 0; w < NQ; w++) {
        float v = acc[w];
        #pragma unroll
        for (int o = 16; o > 0; o >>= 1)
            v += __shfl_xor_sync(0xFFFFFFFF, v, o);
        if ((tid & 31) == 0) red[(tid >> 5) * NQ + w] = v;
    }
    __syncthreads();
    if (tid < NQ) {
        float v = 0.0f;
        #pragma unroll
        for (int r = 0; r < 8; r++) v += red[r * NQ + tid];
        out[b * NQ + tid] = v;
    }
}

extern "C" void kernel_launch(void* const* d_in, const int* in_sizes, int n_in,
                              void* d_out, int out_size)
{
    const float* x   = (const float*)d_in[0];   // [B, 14]
    const float* wts = (const float*)d_in[1];   // [2, 14]
    float* out = (float*)d_out;                 // [B, 14]
    int B = in_sizes[0] / NQ;

    cudaFuncSetAttribute(qsim_kernel,
                         cudaFuncAttributeMaxDynamicSharedMemorySize, SM_BYTES);
    qsim_kernel<<<B, NTHREADS, SM_BYTES>>>(x, wts, out);
}